// round 16
// baseline (speedup 1.0000x reference)
#include <cuda_runtime.h>
#include <cuda_fp16.h>
#include <cstdint>
#include <float.h>

// ---------------- problem constants ----------------
#define Gn    4
#define Mn    4096
#define Dn    128
#define NPG   16384
#define NTILE 128              // queries per CTA
#define BM    64               // codes per streamed B tile
#define MH    2048             // codes per M-half
#define NT_H  (MH / BM)        // 32 tiles per half
#define KCH   8                // 8 k16 chunks (K=128)
#define THREADS 256
#define NPAIRS (Gn * (NPG / NTILE))   // 512 (n0, g) pairs

#define XQ_SIZE  (NPG * Gn * Dn)
#define IND_BASE (XQ_SIZE)
#define CNT_BASE (XQ_SIZE + NPG * Gn)

#define SCORE_BIAS 512.0f      // makes scores positive
#define RESCUE_TAU 1.0f        // fp16 noise + f16-accum + 12-bit key masking

// ---------------- device scratch (allocation-free) ----------------
__device__ float  g_e2[Gn * Mn];       // exact, for rescue
__device__ float  g_e2b[Gn * Mn];      // e2 + SCORE_BIAS, for epilogue
__device__ __half g_Es[(size_t)Gn * Mn * Dn];    // fp16(e)
__device__ uint4  g_top[(size_t)NPG * Gn * 2];   // per (row, m-half): top-4 packed keys
__device__ int    g_sync[NPAIRS];      // arrival counters (self-resetting)

// ---------------- smem layout (dynamic), per CTA = 66048 B ----------------
#define A_OFF   0               // 32 KB
#define B_OFF0  32768           // 16 KB
#define B_OFF1  49152           // 16 KB
#define E2_OFF  65536           // 2 x 64 floats
#define SMEM_TOTAL 66048

// ---------------- PTX helpers ----------------
__device__ __forceinline__ uint32_t smem_u32(const void* p) {
    uint32_t a;
    asm("{ .reg .u64 t; cvta.to.shared.u64 t, %1; cvt.u32.u64 %0, t; }" : "=r"(a) : "l"(p));
    return a;
}
__device__ __forceinline__ void ldsm_x4(uint32_t* r, uint32_t a) {
    asm volatile("ldmatrix.sync.aligned.m8n8.x4.shared.b16 {%0,%1,%2,%3}, [%4];"
                 : "=r"(r[0]), "=r"(r[1]), "=r"(r[2]), "=r"(r[3]) : "r"(a));
}
// f16-accumulate HMMA: D,C are 2 x f16x2 regs (rate-neutral, frees regs)
__device__ __forceinline__ void mma16816h(uint32_t* d, const uint32_t* a, uint32_t b0, uint32_t b1) {
    asm volatile("mma.sync.aligned.m16n8k16.row.col.f16.f16.f16.f16 "
                 "{%0,%1}, {%2,%3,%4,%5}, {%6,%7}, {%0,%1};"
                 : "+r"(d[0]), "+r"(d[1])
                 : "r"(a[0]), "r"(a[1]), "r"(a[2]), "r"(a[3]), "r"(b0), "r"(b1));
}
__device__ __forceinline__ void cp16(uint32_t dst, const void* src) {
    asm volatile("cp.async.cg.shared.global [%0], [%1], 16;" :: "r"(dst), "l"(src));
}
__device__ __forceinline__ void cp4(uint32_t dst, const void* src) {
    asm volatile("cp.async.ca.shared.global [%0], [%1], 4;" :: "r"(dst), "l"(src));
}
#define CP_COMMIT() asm volatile("cp.async.commit_group;" ::: "memory")
#define CP_WAIT0()  asm volatile("cp.async.wait_group 0;" ::: "memory")

__device__ __forceinline__ uint32_t pack_h2(float a, float b) {
    __half2 h = __floats2half2_rn(a, b);
    return *(uint32_t*)&h;
}

// ---------------------------------------------------------------------------
// prep: E -> fp16(e), e2 (raw + biased), count copy.  (X handled inside vq.)
// ---------------------------------------------------------------------------
__global__ void prep_kernel(const float* __restrict__ emb,
                            const float* __restrict__ count,
                            float* __restrict__ out) {
    int gt   = blockIdx.x * blockDim.x + threadIdx.x;
    int r    = gt >> 5;
    int lane = gt & 31;
    if (gt < Gn * Mn) out[CNT_BASE + gt] = count[gt];
    if (r >= Gn * Mn) return;

    float4 v = ((const float4*)(emb + (size_t)r * Dn))[lane];
    float s = v.x * v.x + v.y * v.y + v.z * v.z + v.w * v.w;
    #pragma unroll
    for (int o = 16; o; o >>= 1) s += __shfl_xor_sync(0xffffffffu, s, o);
    if (lane == 0) { g_e2[r] = s; g_e2b[r] = s + SCORE_BIAS; }
    uint2 p;
    p.x = pack_h2(v.x, v.y);
    p.y = pack_h2(v.z, v.w);
    ((uint2*)(g_Es + (size_t)r * Dn))[lane] = p;
}

// ---------------------------------------------------------------------------
// vq: fp16 HMMA (f16 accum), register-resident A (fp32 x converted in-kernel),
// 2 CTAs/SM.  FUSED TAIL: second-arriving m-half CTA of each (n0,g) pair
// merges both halves' top-4, rescues, gathers x_quant, and histograms —
// overlapped with other CTAs' MMA work.  grid = 1024 CTAs, 256 threads.
// ---------------------------------------------------------------------------
__global__ __launch_bounds__(THREADS, 2)
void vq_kernel(const float* __restrict__ x,
               const float* __restrict__ emb,
               float* __restrict__ out) {
    extern __shared__ char sm[];
    const uint32_t sb   = smem_u32(sm);
    const int tid  = threadIdx.x;
    const int lane = tid & 31;
    const int wid  = tid >> 5;
    const int wrow = wid >> 1;              // 0..3  (32-query band)
    const int wcol = wid & 1;               // 0..1  (32-code band)
    const int g    = blockIdx.y;
    const int n0   = blockIdx.x * NTILE;
    const int mh   = blockIdx.z;
    const int mh0  = mh * MH;

    const uint4* Bsrc = (const uint4*)(g_Es + ((size_t)g * Mn + mh0) * Dn);
    auto load_B = [&](int t) {
        const uint32_t boff = (t & 1) ? B_OFF1 : B_OFF0;
        const int m0 = t * BM;
        #pragma unroll
        for (int it = 0; it < 4; it++) {
            int ch = tid + it * THREADS;       // 1024 x 16B, gmem-coalesced
            int r = ch >> 4, j = ch & 15;      // r 0..63
            int c = j >> 1, h = j & 1;
            uint32_t dst = sb + boff + c * 2048 + r * 32 + ((h * 16) ^ ((r & 4) ? 16 : 0));
            cp16(dst, Bsrc + (size_t)(m0 + r) * 16 + j);
        }
        if (tid < BM) cp4(sb + E2_OFF + (t & 1) * 256 + tid * 4,
                          g_e2b + g * Mn + mh0 + m0 + tid);
    };

    load_B(0); CP_COMMIT();                  // overlap with A staging

    // ---- A stage (once): read fp32 x, convert to fp16(-2x), swizzled STS ----
    {
        #pragma unroll
        for (int it = 0; it < 8; it++) {
            int ch = tid + it * THREADS;       // 2048 chunks of 16B output
            int r = ch & 127, j = ch >> 7;     // j 0..15 (8 floats each)
            const float4* src = (const float4*)(x + ((size_t)(n0 + r) * Gn + g) * Dn + j * 8);
            float4 v0 = src[0], v1 = src[1];   // 32B aligned sector loads
            uint4 p;
            p.x = pack_h2(-2.f * v0.x, -2.f * v0.y);
            p.y = pack_h2(-2.f * v0.z, -2.f * v0.w);
            p.z = pack_h2(-2.f * v1.x, -2.f * v1.y);
            p.w = pack_h2(-2.f * v1.z, -2.f * v1.w);
            int c = j >> 1, h = j & 1;
            uint32_t off = c * 4096 + r * 32 + ((h * 16) ^ ((r & 4) ? 16 : 0));
            *(uint4*)(sm + A_OFF + off) = p;
        }
    }
    __syncthreads();

    // ---- preload ALL A fragments into registers (constant across tiles) ----
    const int lr  = (lane & 7) + ((lane >> 3) & 1) * 8;   // row-in-16
    const int lkh = lane >> 4;                            // k half (0/1)
    uint32_t af[2][KCH][4];
    #pragma unroll
    for (int i = 0; i < 2; i++) {
        int ar = wrow * 32 + i * 16 + lr;
        uint32_t ab = sb + A_OFF + ar * 32 + ((lkh * 16) ^ ((ar & 4) ? 16 : 0));
        #pragma unroll
        for (int ks = 0; ks < KCH; ks++) ldsm_x4(af[i][ks], ab + ks * 4096);
    }

    uint32_t b_off[2];
    #pragma unroll
    for (int f = 0; f < 2; f++) {
        int bc = wcol * 32 + f * 16 + lr;                 // 0..63
        b_off[f] = bc * 32 + ((lkh * 16) ^ ((bc & 4) ? 16 : 0));
    }

    // packed top-2 keys per row-slot: (score_bits & ~0xFFF) | code_idx(global)
    uint32_t k1[4], k2[4];
    #pragma unroll
    for (int s = 0; s < 4; s++) { k1[s] = 0xFFFFFFFFu; k2[s] = 0xFFFFFFFFu; }

    for (int t = 0; t < NT_H; t++) {
        CP_WAIT0();
        __syncthreads();                 // tile t resident; prev buffer free
        if (t + 1 < NT_H) { load_B(t + 1); CP_COMMIT(); }

        const uint32_t bb = sb + ((t & 1) ? B_OFF1 : B_OFF0);
        uint32_t acc[2][4][2];           // f16x2 accumulators
        #pragma unroll
        for (int i = 0; i < 2; i++)
            #pragma unroll
            for (int j = 0; j < 4; j++) { acc[i][j][0] = 0u; acc[i][j][1] = 0u; }

        #pragma unroll
        for (int ks = 0; ks < KCH; ks++) {
            uint32_t bh[2][4];
            #pragma unroll
            for (int f = 0; f < 2; f++) ldsm_x4(bh[f], bb + b_off[f] + ks * 2048);
            #pragma unroll
            for (int i = 0; i < 2; i++)
                #pragma unroll
                for (int f = 0; f < 2; f++) {
                    mma16816h(acc[i][f * 2 + 0], af[i][ks], bh[f][0], bh[f][2]);
                    mma16816h(acc[i][f * 2 + 1], af[i][ks], bh[f][1], bh[f][3]);
                }
        }

        // ---- epilogue: key = pack(e2b + dot, idx); branchless top-2 ----
        const float* e2s = (const float*)(sm + E2_OFF + (t & 1) * 256);
        const int mbase = mh0 + t * BM;
        #pragma unroll
        for (int jf = 0; jf < 4; jf++) {
            int c0 = wcol * 32 + (jf >> 1) * 16 + (jf & 1) * 8 + (lane & 3) * 2;
            float ea = e2s[c0], eb = e2s[c0 + 1];
            uint32_t ia = (uint32_t)(mbase + c0), ib = ia + 1;
            #pragma unroll
            for (int i = 0; i < 2; i++)
                #pragma unroll
                for (int rh = 0; rh < 2; rh++) {
                    int s = i * 2 + rh;
                    float2 fp = __half22float2(*(const __half2*)&acc[i][jf][rh]);
                    uint32_t ka = (__float_as_uint(fp.x + ea) & ~0xFFFu) | ia;
                    uint32_t kb = (__float_as_uint(fp.y + eb) & ~0xFFFu) | ib;
                    k2[s] = min(k2[s], max(k1[s], ka));
                    k1[s] = min(k1[s], ka);
                    k2[s] = min(k2[s], max(k1[s], kb));
                    k1[s] = min(k1[s], kb);
                }
        }
    }

    // ---- cross-lane/warp reduction: 16 keys/row -> row top-4 -> g_top ----
    uint2* red = (uint2*)(sm + B_OFF0);      // [128 rows][8 slots] = 8 KB
    #pragma unroll
    for (int s = 0; s < 4; s++) {
        int row  = wrow * 32 + (s >> 1) * 16 + (s & 1) * 8 + (lane >> 2);
        int slot = wcol * 4 + (lane & 3);
        red[row * 8 + slot] = make_uint2(k1[s], k2[s]);
    }
    __syncthreads();

    if (tid < NTILE) {
        uint32_t tk[4] = {0xFFFFFFFFu, 0xFFFFFFFFu, 0xFFFFFFFFu, 0xFFFFFFFFu};
        auto ins = [&](uint32_t k) {
            if (k < tk[3]) {
                tk[3] = k;
                #pragma unroll
                for (int q = 3; q > 0; q--)
                    if (tk[q] < tk[q-1]) { uint32_t f = tk[q]; tk[q] = tk[q-1]; tk[q-1] = f; }
            }
        };
        #pragma unroll 4
        for (int q = 0; q < 8; q++) {
            uint2 c = red[tid * 8 + q];
            ins(c.x); ins(c.y);
        }
        g_top[((size_t)(g * NPG + n0 + tid)) * 2 + mh] =
            make_uint4(tk[0], tk[1], tk[2], tk[3]);
    }

    // ---- pair arrival: second CTA of this (n0, g) pair runs the merge ----
    __threadfence();                         // publish g_top writes
    __syncthreads();
    __shared__ int s_old;
    const int pair = g * (NPG / NTILE) + blockIdx.x;
    if (tid == 0) s_old = atomicAdd(&g_sync[pair], 1);
    __syncthreads();
    if (s_old == 0) return;                  // first arriver exits
    if (tid == 0) g_sync[pair] = 0;          // self-reset for graph replays
    __threadfence();                         // acquire peer's g_top writes

    // ---- fused merge + rescue + gather + histogram (16 rows per warp) ----
    for (int rr = 0; rr < 16; rr++) {
        const int row = wid * 16 + rr;
        const int n   = n0 + row;
        const uint4 h0 = g_top[((size_t)(g * NPG + n)) * 2 + 0];
        const uint4 h1 = g_top[((size_t)(g * NPG + n)) * 2 + 1];
        uint32_t tk[4] = {0xFFFFFFFFu, 0xFFFFFFFFu, 0xFFFFFFFFu, 0xFFFFFFFFu};
        auto ins = [&](uint32_t k) {
            if (k < tk[3]) {
                tk[3] = k;
                #pragma unroll
                for (int q = 3; q > 0; q--)
                    if (tk[q] < tk[q-1]) { uint32_t f = tk[q]; tk[q] = tk[q-1]; tk[q-1] = f; }
            }
        };
        ins(h0.x); ins(h0.y); ins(h0.z); ins(h0.w);
        ins(h1.x); ins(h1.y); ins(h1.z); ins(h1.w);

        int best = (int)(tk[0] & 0xFFFu);
        float tv0 = __uint_as_float(tk[0] & ~0xFFFu);
        float tv1 = __uint_as_float(tk[1] & ~0xFFFu);

        if (tv1 - tv0 < RESCUE_TAU) {        // warp-cooperative exact rescore
            float4 xv = ((const float4*)(x + ((size_t)n * Gn + g) * Dn))[lane];
            float bs = FLT_MAX; int bi = 0x7FFFFFFF;
            #pragma unroll
            for (int c = 0; c < 4; c++) {
                int cand = (int)(tk[c] & 0xFFFu);
                float4 ev = ((const float4*)(emb + ((size_t)(g * Mn + cand)) * Dn))[lane];
                float d = fmaf(xv.x, ev.x, fmaf(xv.y, ev.y, fmaf(xv.z, ev.z, xv.w * ev.w)));
                #pragma unroll
                for (int o = 16; o; o >>= 1) d += __shfl_xor_sync(0xffffffffu, d, o);
                float sc = fmaf(-2.f, d, g_e2[g * Mn + cand]);
                if (sc < bs || (sc == bs && cand < bi)) { bs = sc; bi = cand; }
            }
            best = bi;
        }

        const float4* src = (const float4*)(emb + ((size_t)(g * Mn + best)) * Dn);
        ((float4*)(out + ((size_t)n * Gn + g) * Dn))[lane] = src[lane];
        if (lane == 0) {
            out[IND_BASE + (size_t)n * Gn + g] = (float)best;
            atomicAdd(&out[CNT_BASE + g * Mn + best], 1.0f);
        }
    }
}

// ---------------------------------------------------------------------------
extern "C" void kernel_launch(void* const* d_in, const int* in_sizes, int n_in,
                              void* d_out, int out_size) {
    const float* x     = (const float*)d_in[0];
    const float* emb   = (const float*)d_in[1];
    const float* count = (const float*)d_in[2];
    float*       out   = (float*)d_out;

    cudaFuncSetAttribute(vq_kernel,
                         cudaFuncAttributeMaxDynamicSharedMemorySize, SMEM_TOTAL);

    // prep covers E rows (+ count copy): 16384 warps
    prep_kernel<<<(Gn * Mn * 32) / 256, 256>>>(emb, count, out);

    dim3 grid(NPG / NTILE, Gn, 2);
    vq_kernel<<<grid, THREADS, SMEM_TOTAL>>>(x, emb, out);
}

// round 17
// speedup vs baseline: 1.2701x; 1.2701x over previous
#include <cuda_runtime.h>
#include <cuda_fp16.h>
#include <cstdint>
#include <float.h>

// ---------------- problem constants ----------------
#define Gn    4
#define Mn    4096
#define Dn    128
#define NPG   16384
#define NTILE 128              // queries per CTA
#define BM    64               // codes per streamed B tile
#define MH    2048             // codes per M-half
#define NT_H  (MH / BM)        // 32 tiles per half
#define KCH   8                // 8 k16 chunks (K=128)
#define THREADS 256

#define XQ_SIZE  (NPG * Gn * Dn)
#define IND_BASE (XQ_SIZE)
#define CNT_BASE (XQ_SIZE + NPG * Gn)

#define SCORE_BIAS 512.0f      // makes scores positive
#define RESCUE_TAU 1.0f        // fp16 noise + f16-accum + 12-bit key masking

// ---------------- device scratch (allocation-free) ----------------
__device__ float  g_e2[Gn * Mn];       // exact, for rescue
__device__ float  g_e2b[Gn * Mn];      // e2 + SCORE_BIAS, for epilogue
__device__ __half g_Es[(size_t)Gn * Mn * Dn];    // fp16(e)
__device__ uint4  g_top[(size_t)NPG * Gn * 2];   // per (row, m-half): top-4 packed keys

// ---------------- smem layout (dynamic), per CTA = 66048 B ----------------
#define A_OFF   0               // 32 KB
#define B_OFF0  32768           // 16 KB
#define B_OFF1  49152           // 16 KB
#define E2_OFF  65536           // 2 x 64 floats
#define SMEM_TOTAL 66048

// ---------------- PTX helpers ----------------
__device__ __forceinline__ uint32_t smem_u32(const void* p) {
    uint32_t a;
    asm("{ .reg .u64 t; cvta.to.shared.u64 t, %1; cvt.u32.u64 %0, t; }" : "=r"(a) : "l"(p));
    return a;
}
__device__ __forceinline__ void ldsm_x4(uint32_t* r, uint32_t a) {
    asm volatile("ldmatrix.sync.aligned.m8n8.x4.shared.b16 {%0,%1,%2,%3}, [%4];"
                 : "=r"(r[0]), "=r"(r[1]), "=r"(r[2]), "=r"(r[3]) : "r"(a));
}
// f16-accumulate HMMA: D,C are 2 x f16x2 regs (rate-neutral, frees regs)
__device__ __forceinline__ void mma16816h(uint32_t* d, const uint32_t* a, uint32_t b0, uint32_t b1) {
    asm volatile("mma.sync.aligned.m16n8k16.row.col.f16.f16.f16.f16 "
                 "{%0,%1}, {%2,%3,%4,%5}, {%6,%7}, {%0,%1};"
                 : "+r"(d[0]), "+r"(d[1])
                 : "r"(a[0]), "r"(a[1]), "r"(a[2]), "r"(a[3]), "r"(b0), "r"(b1));
}
__device__ __forceinline__ void cp16(uint32_t dst, const void* src) {
    asm volatile("cp.async.cg.shared.global [%0], [%1], 16;" :: "r"(dst), "l"(src));
}
__device__ __forceinline__ void cp4(uint32_t dst, const void* src) {
    asm volatile("cp.async.ca.shared.global [%0], [%1], 4;" :: "r"(dst), "l"(src));
}
#define CP_COMMIT() asm volatile("cp.async.commit_group;" ::: "memory")
#define CP_WAIT0()  asm volatile("cp.async.wait_group 0;" ::: "memory")

__device__ __forceinline__ uint32_t pack_h2(float a, float b) {
    __half2 h = __floats2half2_rn(a, b);
    return *(uint32_t*)&h;
}

// ---------------------------------------------------------------------------
// prep: E -> fp16(e), e2 (raw + biased), count copy.  (X handled inside vq.)
// Triggers programmatic launch completion immediately so vq can start its
// prep-independent A-staging concurrently.
// ---------------------------------------------------------------------------
__global__ void prep_kernel(const float* __restrict__ emb,
                            const float* __restrict__ count,
                            float* __restrict__ out) {
    cudaTriggerProgrammaticLaunchCompletion();
    int gt   = blockIdx.x * blockDim.x + threadIdx.x;
    int r    = gt >> 5;
    int lane = gt & 31;
    if (gt < Gn * Mn) out[CNT_BASE + gt] = count[gt];
    if (r >= Gn * Mn) return;

    float4 v = ((const float4*)(emb + (size_t)r * Dn))[lane];
    float s = v.x * v.x + v.y * v.y + v.z * v.z + v.w * v.w;
    #pragma unroll
    for (int o = 16; o; o >>= 1) s += __shfl_xor_sync(0xffffffffu, s, o);
    if (lane == 0) { g_e2[r] = s; g_e2b[r] = s + SCORE_BIAS; }
    uint2 p;
    p.x = pack_h2(v.x, v.y);
    p.y = pack_h2(v.z, v.w);
    ((uint2*)(g_Es + (size_t)r * Dn))[lane] = p;
}

// ---------------------------------------------------------------------------
// vq: fp16 HMMA (f16 accum), register-resident A (fp32 x converted in-kernel),
// 2 CTAs/SM (co-resident CTA hides epilogue tail).  PDL: A-staging runs
// before cudaGridDependencySynchronize so it overlaps prep.
// 8 warps in 4x2 grid (warp tile 32q x 32c); BM=64 double-buffered.
// grid = (128 n-tiles, 4 groups, 2 m-halves) = 1024 CTAs.
// ---------------------------------------------------------------------------
__global__ __launch_bounds__(THREADS, 2)
void vq_kernel(const float* __restrict__ x) {
    extern __shared__ char sm[];
    const uint32_t sb   = smem_u32(sm);
    const int tid  = threadIdx.x;
    const int lane = tid & 31;
    const int wid  = tid >> 5;
    const int wrow = wid >> 1;              // 0..3  (32-query band)
    const int wcol = wid & 1;               // 0..1  (32-code band)
    const int g    = blockIdx.y;
    const int n0   = blockIdx.x * NTILE;
    const int mh   = blockIdx.z;
    const int mh0  = mh * MH;

    // ---- A stage (prep-independent): fp32 x -> fp16(-2x), swizzled STS ----
    {
        #pragma unroll
        for (int it = 0; it < 8; it++) {
            int ch = tid + it * THREADS;       // 2048 chunks of 16B output
            int r = ch & 127, j = ch >> 7;     // j 0..15 (8 floats each)
            const float4* src = (const float4*)(x + ((size_t)(n0 + r) * Gn + g) * Dn + j * 8);
            float4 v0 = src[0], v1 = src[1];   // 32B aligned sector loads
            uint4 p;
            p.x = pack_h2(-2.f * v0.x, -2.f * v0.y);
            p.y = pack_h2(-2.f * v0.z, -2.f * v0.w);
            p.z = pack_h2(-2.f * v1.x, -2.f * v1.y);
            p.w = pack_h2(-2.f * v1.z, -2.f * v1.w);
            int c = j >> 1, h = j & 1;
            uint32_t off = c * 4096 + r * 32 + ((h * 16) ^ ((r & 4) ? 16 : 0));
            *(uint4*)(sm + A_OFF + off) = p;
        }
    }
    __syncthreads();

    // ---- wait for prep's g_Es / g_e2b to be globally visible ----
    cudaGridDependencySynchronize();

    const uint4* Bsrc = (const uint4*)(g_Es + ((size_t)g * Mn + mh0) * Dn);
    auto load_B = [&](int t) {
        const uint32_t boff = (t & 1) ? B_OFF1 : B_OFF0;
        const int m0 = t * BM;
        #pragma unroll
        for (int it = 0; it < 4; it++) {
            int ch = tid + it * THREADS;       // 1024 x 16B, gmem-coalesced
            int r = ch >> 4, j = ch & 15;      // r 0..63
            int c = j >> 1, h = j & 1;
            uint32_t dst = sb + boff + c * 2048 + r * 32 + ((h * 16) ^ ((r & 4) ? 16 : 0));
            cp16(dst, Bsrc + (size_t)(m0 + r) * 16 + j);
        }
        if (tid < BM) cp4(sb + E2_OFF + (t & 1) * 256 + tid * 4,
                          g_e2b + g * Mn + mh0 + m0 + tid);
    };

    load_B(0); CP_COMMIT();

    // ---- preload ALL A fragments into registers (constant across tiles) ----
    const int lr  = (lane & 7) + ((lane >> 3) & 1) * 8;   // row-in-16
    const int lkh = lane >> 4;                            // k half (0/1)
    uint32_t af[2][KCH][4];
    #pragma unroll
    for (int i = 0; i < 2; i++) {
        int ar = wrow * 32 + i * 16 + lr;
        uint32_t ab = sb + A_OFF + ar * 32 + ((lkh * 16) ^ ((ar & 4) ? 16 : 0));
        #pragma unroll
        for (int ks = 0; ks < KCH; ks++) ldsm_x4(af[i][ks], ab + ks * 4096);
    }

    uint32_t b_off[2];
    #pragma unroll
    for (int f = 0; f < 2; f++) {
        int bc = wcol * 32 + f * 16 + lr;                 // 0..63
        b_off[f] = bc * 32 + ((lkh * 16) ^ ((bc & 4) ? 16 : 0));
    }

    // packed top-2 keys per row-slot: (score_bits & ~0xFFF) | code_idx(global)
    uint32_t k1[4], k2[4];
    #pragma unroll
    for (int s = 0; s < 4; s++) { k1[s] = 0xFFFFFFFFu; k2[s] = 0xFFFFFFFFu; }

    for (int t = 0; t < NT_H; t++) {
        CP_WAIT0();
        __syncthreads();                 // tile t resident; prev buffer free
        if (t + 1 < NT_H) { load_B(t + 1); CP_COMMIT(); }

        const uint32_t bb = sb + ((t & 1) ? B_OFF1 : B_OFF0);
        uint32_t acc[2][4][2];           // f16x2 accumulators
        #pragma unroll
        for (int i = 0; i < 2; i++)
            #pragma unroll
            for (int j = 0; j < 4; j++) { acc[i][j][0] = 0u; acc[i][j][1] = 0u; }

        #pragma unroll
        for (int ks = 0; ks < KCH; ks++) {
            uint32_t bh[2][4];
            #pragma unroll
            for (int f = 0; f < 2; f++) ldsm_x4(bh[f], bb + b_off[f] + ks * 2048);
            #pragma unroll
            for (int i = 0; i < 2; i++)
                #pragma unroll
                for (int f = 0; f < 2; f++) {
                    mma16816h(acc[i][f * 2 + 0], af[i][ks], bh[f][0], bh[f][2]);
                    mma16816h(acc[i][f * 2 + 1], af[i][ks], bh[f][1], bh[f][3]);
                }
        }

        // ---- epilogue: key = pack(e2b + dot, idx); branchless top-2 ----
        const float* e2s = (const float*)(sm + E2_OFF + (t & 1) * 256);
        const int mbase = mh0 + t * BM;
        #pragma unroll
        for (int jf = 0; jf < 4; jf++) {
            int c0 = wcol * 32 + (jf >> 1) * 16 + (jf & 1) * 8 + (lane & 3) * 2;
            float ea = e2s[c0], eb = e2s[c0 + 1];
            uint32_t ia = (uint32_t)(mbase + c0), ib = ia + 1;
            #pragma unroll
            for (int i = 0; i < 2; i++)
                #pragma unroll
                for (int rh = 0; rh < 2; rh++) {
                    int s = i * 2 + rh;
                    float2 fp = __half22float2(*(const __half2*)&acc[i][jf][rh]);
                    uint32_t ka = (__float_as_uint(fp.x + ea) & ~0xFFFu) | ia;
                    uint32_t kb = (__float_as_uint(fp.y + eb) & ~0xFFFu) | ib;
                    k2[s] = min(k2[s], max(k1[s], ka));
                    k1[s] = min(k1[s], ka);
                    k2[s] = min(k2[s], max(k1[s], kb));
                    k1[s] = min(k1[s], kb);
                }
        }
    }

    // ---- cross-lane/warp reduction: 16 keys/row -> row top-4 -> g_top ----
    __syncthreads();
    uint2* red = (uint2*)(sm + B_OFF0);      // [128 rows][8 slots] = 8 KB
    #pragma unroll
    for (int s = 0; s < 4; s++) {
        int row  = wrow * 32 + (s >> 1) * 16 + (s & 1) * 8 + (lane >> 2);
        int slot = wcol * 4 + (lane & 3);
        red[row * 8 + slot] = make_uint2(k1[s], k2[s]);
    }
    __syncthreads();

    if (tid < NTILE) {
        uint32_t tk[4] = {0xFFFFFFFFu, 0xFFFFFFFFu, 0xFFFFFFFFu, 0xFFFFFFFFu};
        auto ins = [&](uint32_t k) {
            if (k < tk[3]) {
                tk[3] = k;
                #pragma unroll
                for (int q = 3; q > 0; q--)
                    if (tk[q] < tk[q-1]) { uint32_t f = tk[q]; tk[q] = tk[q-1]; tk[q-1] = f; }
            }
        };
        #pragma unroll 4
        for (int q = 0; q < 8; q++) {
            uint2 c = red[tid * 8 + q];
            ins(c.x); ins(c.y);
        }
        g_top[((size_t)(g * NPG + n0 + tid)) * 2 + mh] =
            make_uint4(tk[0], tk[1], tk[2], tk[3]);
    }
}

// ---------------------------------------------------------------------------
// merge halves + rescue + gather + histogram (one warp per (n,g) row)
// ---------------------------------------------------------------------------
__global__ void merge_gather_kernel(const float* __restrict__ x,
                                    const float* __restrict__ emb,
                                    float* __restrict__ out) {
    int w    = (blockIdx.x * blockDim.x + threadIdx.x) >> 5;
    int lane = threadIdx.x & 31;
    if (w >= NPG * Gn) return;
    int g = w & 3, n = w >> 2;

    const uint4 h0 = g_top[((size_t)(g * NPG + n)) * 2 + 0];
    const uint4 h1 = g_top[((size_t)(g * NPG + n)) * 2 + 1];
    uint32_t tk[4] = {0xFFFFFFFFu, 0xFFFFFFFFu, 0xFFFFFFFFu, 0xFFFFFFFFu};
    auto ins = [&](uint32_t k) {
        if (k < tk[3]) {
            tk[3] = k;
            #pragma unroll
            for (int q = 3; q > 0; q--)
                if (tk[q] < tk[q-1]) { uint32_t f = tk[q]; tk[q] = tk[q-1]; tk[q-1] = f; }
        }
    };
    ins(h0.x); ins(h0.y); ins(h0.z); ins(h0.w);
    ins(h1.x); ins(h1.y); ins(h1.z); ins(h1.w);

    int best = (int)(tk[0] & 0xFFFu);
    float tv0 = __uint_as_float(tk[0] & ~0xFFFu);
    float tv1 = __uint_as_float(tk[1] & ~0xFFFu);

    if (tv1 - tv0 < RESCUE_TAU) {            // warp-cooperative exact rescore
        float4 xv = ((const float4*)(x + ((size_t)n * Gn + g) * Dn))[lane];
        float bs = FLT_MAX; int bi = 0x7FFFFFFF;
        #pragma unroll
        for (int c = 0; c < 4; c++) {
            int cand = (int)(tk[c] & 0xFFFu);
            float4 ev = ((const float4*)(emb + ((size_t)(g * Mn + cand)) * Dn))[lane];
            float d = fmaf(xv.x, ev.x, fmaf(xv.y, ev.y, fmaf(xv.z, ev.z, xv.w * ev.w)));
            #pragma unroll
            for (int o = 16; o; o >>= 1) d += __shfl_xor_sync(0xffffffffu, d, o);
            float sc = fmaf(-2.f, d, g_e2[g * Mn + cand]);
            if (sc < bs || (sc == bs && cand < bi)) { bs = sc; bi = cand; }
        }
        best = bi;
    }

    // gather x_quant row + index + histogram
    const float4* src = (const float4*)(emb + ((size_t)(g * Mn + best)) * Dn);
    ((float4*)(out + (size_t)w * Dn))[lane] = src[lane];
    if (lane == 0) {
        out[IND_BASE + w] = (float)best;
        atomicAdd(&out[CNT_BASE + g * Mn + best], 1.0f);
    }
}

// ---------------------------------------------------------------------------
extern "C" void kernel_launch(void* const* d_in, const int* in_sizes, int n_in,
                              void* d_out, int out_size) {
    const float* x     = (const float*)d_in[0];
    const float* emb   = (const float*)d_in[1];
    const float* count = (const float*)d_in[2];
    float*       out   = (float*)d_out;

    cudaFuncSetAttribute(vq_kernel,
                         cudaFuncAttributeMaxDynamicSharedMemorySize, SMEM_TOTAL);

    // prep covers E rows (+ count copy): 16384 warps
    prep_kernel<<<(Gn * Mn * 32) / 256, 256>>>(emb, count, out);

    // vq with programmatic dependent launch: A-staging overlaps prep
    {
        cudaLaunchConfig_t cfg = {};
        cfg.gridDim  = dim3(NPG / NTILE, Gn, 2);
        cfg.blockDim = dim3(THREADS, 1, 1);
        cfg.dynamicSmemBytes = SMEM_TOTAL;
        cfg.stream = 0;
        cudaLaunchAttribute attr[1];
        attr[0].id = cudaLaunchAttributeProgrammaticStreamSerialization;
        attr[0].val.programmaticStreamSerializationAllowed = 1;
        cfg.attrs = attr;
        cfg.numAttrs = 1;
        cudaLaunchKernelEx(&cfg, vq_kernel, x);
    }

    merge_gather_kernel<<<(NPG * Gn * 32) / 256, 256>>>(x, emb, out);
}